// round 4
// baseline (speedup 1.0000x reference)
#include <cuda_runtime.h>
#include <cuda_bf16.h>
#include <math.h>

// Problem constants
#define LNUM 4
#define DD   256
#define HH   8
#define INNER 2048
#define MM   1024
#define BB   8
#define NN_  1024
#define ROWS (BB*NN_)       // 8192
#define QKV_N (3*INNER)     // 6144
#define SCALE_ 0.0625f

// ---------------- device scratch ----------------
__device__ float g_h[(size_t)ROWS*DD];
__device__ float g_qkv[(size_t)ROWS*QKV_N];
__device__ float g_scores[(size_t)64*1024*1024];
__device__ float g_attn[(size_t)ROWS*INNER];
__device__ float g_mlp[(size_t)ROWS*MM];

__device__ __forceinline__ unsigned f2tf32(float x) {
    unsigned r;
    asm("cvt.rna.tf32.f32 %0, %1;" : "=r"(r) : "f"(x));
    return r;
}

// ---------------- LayerNorm ----------------
__global__ void ln_kernel(const float* __restrict__ x,
                          const float* __restrict__ g,
                          const float* __restrict__ b,
                          float* __restrict__ out) {
    const int row = blockIdx.x;
    const int t   = threadIdx.x;
    float v = x[(size_t)row*DD + t];
    float s1 = v, s2 = v*v;
    #pragma unroll
    for (int o = 16; o > 0; o >>= 1) {
        s1 += __shfl_down_sync(0xffffffffu, s1, o);
        s2 += __shfl_down_sync(0xffffffffu, s2, o);
    }
    __shared__ float w1[8], w2[8];
    const int lane = t & 31, wid = t >> 5;
    if (lane == 0) { w1[wid] = s1; w2[wid] = s2; }
    __syncthreads();
    __shared__ float smu, srs;
    if (t == 0) {
        float a = 0.f, c = 0.f;
        #pragma unroll
        for (int i = 0; i < 8; i++) { a += w1[i]; c += w2[i]; }
        float mu  = a / DD;
        float var = c / DD - mu*mu;
        smu = mu;
        srs = rsqrtf(var + 1e-5f);
    }
    __syncthreads();
    out[(size_t)row*DD + t] = (v - smu) * srs * g[t] + b[t];
}

// ---------------- softmax over 1024 cols ----------------
__global__ void softmax_kernel(float* __restrict__ s) {
    float* p = s + (size_t)blockIdx.x * 1024;
    const int t = threadIdx.x;
    float v0 = p[t], v1 = p[t+256], v2 = p[t+512], v3 = p[t+768];
    float m = fmaxf(fmaxf(v0, v1), fmaxf(v2, v3));
    #pragma unroll
    for (int o = 16; o > 0; o >>= 1) m = fmaxf(m, __shfl_down_sync(0xffffffffu, m, o));
    __shared__ float wm[8];
    const int lane = t & 31, wid = t >> 5;
    if (lane == 0) wm[wid] = m;
    __syncthreads();
    __shared__ float bm;
    if (t == 0) {
        float a = wm[0];
        #pragma unroll
        for (int i = 1; i < 8; i++) a = fmaxf(a, wm[i]);
        bm = a;
    }
    __syncthreads();
    m = bm;
    v0 = expf(v0 - m); v1 = expf(v1 - m); v2 = expf(v2 - m); v3 = expf(v3 - m);
    float s1 = v0 + v1 + v2 + v3;
    #pragma unroll
    for (int o = 16; o > 0; o >>= 1) s1 += __shfl_down_sync(0xffffffffu, s1, o);
    __shared__ float ws[8];
    if (lane == 0) ws[wid] = s1;
    __syncthreads();
    __shared__ float bs_;
    if (t == 0) {
        float a = 0.f;
        #pragma unroll
        for (int i = 0; i < 8; i++) a += ws[i];
        bs_ = a;
    }
    __syncthreads();
    const float inv = 1.f / bs_;
    p[t] = v0*inv; p[t+256] = v1*inv; p[t+512] = v2*inv; p[t+768] = v3*inv;
}

// ---------------- tf32 tensor-core GEMM, 128x128 block, 32x64 warps -------
// C = alpha * A[M,K] @ op(B) (+bias)(+gelu|+residual); row-major.
// TB=false: B is [K,N]. TB=true: B is [N,K] (computes A @ B^T).
// 8 warps as 4(row) x 2(col); warp tile 32x64; K-chunk 32.
// EPI: 0 none, 1 +bias, 2 +bias+gelu, 3 +bias+residual
template<int EPI, bool TB>
__global__ void __launch_bounds__(256, 2)
gemm_tf32(const float* __restrict__ A, const float* __restrict__ B,
          const float* __restrict__ bias, const float* __restrict__ res,
          float* __restrict__ C,
          int M, int N, int K, int lda, int ldb, int ldc,
          long long sAb, long long sAh, long long sBb, long long sBh,
          long long sCb, long long sCh, float alpha)
{
    const int bb = blockIdx.z >> 3;
    const int hh = blockIdx.z & 7;
    A += (size_t)bb*sAb + (size_t)hh*sAh;
    B += (size_t)bb*sBb + (size_t)hh*sBh;
    C += (size_t)bb*sCb + (size_t)hh*sCh;

    const int row0 = blockIdx.y * 128;
    const int col0 = blockIdx.x * 128;
    const int tid  = threadIdx.x;
    const int lane = tid & 31, wid = tid >> 5;
    const int wr = wid & 3, wc = wid >> 2;   // warp: rows wr*32, cols wc*64
    const int g  = lane >> 2, t4 = lane & 3;

    __shared__ unsigned As[32][129];   // [k][m], pad 129
    __shared__ unsigned Bs[32][129];   // [k][n], pad 129

    // loader geometry (128 rows x 32 cols tiles, 4 float4 per thread)
    const int rA = tid >> 3;          // 0..31
    const int cA = (tid & 7) * 4;     // 0..28
    // [K=32 rows][128 cols] tile geometry (for TB=false B)
    const int rB = tid >> 5;          // 0..7
    const int cB = (tid & 31) * 4;    // 0..124

    float acc[2][8][4] = {};

    for (int kk = 0; kk < K; kk += 32) {
        // ---- A tile: rows row0..row0+127, k cols kk..kk+31 -> As[k][m]
        #pragma unroll
        for (int i = 0; i < 4; i++) {
            const int r = rA + 32*i;
            float4 v = *reinterpret_cast<const float4*>(
                &A[(size_t)(row0 + r)*lda + kk + cA]);
            As[cA+0][r] = f2tf32(v.x);
            As[cA+1][r] = f2tf32(v.y);
            As[cA+2][r] = f2tf32(v.z);
            As[cA+3][r] = f2tf32(v.w);
        }
        // ---- B tile -> Bs[k][n]
        if (TB) {
            // B[N][K]: rows are n, cols are k (A-style geometry)
            #pragma unroll
            for (int i = 0; i < 4; i++) {
                const int r = rA + 32*i;   // n index
                float4 v = *reinterpret_cast<const float4*>(
                    &B[(size_t)(col0 + r)*ldb + kk + cA]);
                Bs[cA+0][r] = f2tf32(v.x);
                Bs[cA+1][r] = f2tf32(v.y);
                Bs[cA+2][r] = f2tf32(v.z);
                Bs[cA+3][r] = f2tf32(v.w);
            }
        } else {
            #pragma unroll
            for (int i = 0; i < 4; i++) {
                const int r = rB + 8*i;    // k index
                float4 v = *reinterpret_cast<const float4*>(
                    &B[(size_t)(kk + r)*ldb + col0 + cB]);
                Bs[r][cB+0] = f2tf32(v.x);
                Bs[r][cB+1] = f2tf32(v.y);
                Bs[r][cB+2] = f2tf32(v.z);
                Bs[r][cB+3] = f2tf32(v.w);
            }
        }
        __syncthreads();

        #pragma unroll
        for (int k8 = 0; k8 < 4; k8++) {
            const int kb = k8*8;
            unsigned a[2][4], b[8][2];
            #pragma unroll
            for (int m = 0; m < 2; m++) {
                const int rm = wr*32 + m*16;
                a[m][0] = As[kb+t4  ][rm+g  ];
                a[m][1] = As[kb+t4  ][rm+g+8];
                a[m][2] = As[kb+t4+4][rm+g  ];
                a[m][3] = As[kb+t4+4][rm+g+8];
            }
            #pragma unroll
            for (int n = 0; n < 8; n++) {
                const int cn = wc*64 + n*8 + g;
                b[n][0] = Bs[kb+t4  ][cn];
                b[n][1] = Bs[kb+t4+4][cn];
            }
            #pragma unroll
            for (int m = 0; m < 2; m++)
                #pragma unroll
                for (int n = 0; n < 8; n++)
                    asm volatile(
                        "mma.sync.aligned.m16n8k8.row.col.f32.tf32.tf32.f32 "
                        "{%0,%1,%2,%3}, {%4,%5,%6,%7}, {%8,%9}, {%0,%1,%2,%3};"
                        : "+f"(acc[m][n][0]), "+f"(acc[m][n][1]),
                          "+f"(acc[m][n][2]), "+f"(acc[m][n][3])
                        : "r"(a[m][0]), "r"(a[m][1]), "r"(a[m][2]), "r"(a[m][3]),
                          "r"(b[n][0]), "r"(b[n][1]));
        }
        __syncthreads();
    }

    // epilogue
    #pragma unroll
    for (int m = 0; m < 2; m++) {
        const int rbase = row0 + wr*32 + m*16 + g;
        #pragma unroll
        for (int n = 0; n < 8; n++) {
            const int c = col0 + wc*64 + n*8 + 2*t4;
            #pragma unroll
            for (int h = 0; h < 2; h++) {
                const int r = rbase + h*8;
                float v0 = acc[m][n][2*h+0] * alpha;
                float v1 = acc[m][n][2*h+1] * alpha;
                if (EPI >= 1) { v0 += bias[c]; v1 += bias[c+1]; }
                if (EPI == 2) {
                    v0 = 0.5f * v0 * (1.0f + erff(v0 * 0.70710678118654752f));
                    v1 = 0.5f * v1 * (1.0f + erff(v1 * 0.70710678118654752f));
                }
                if (EPI == 3) {
                    v0 += res[(size_t)r*ldc + c];
                    v1 += res[(size_t)r*ldc + c + 1];
                }
                *reinterpret_cast<float2*>(&C[(size_t)r*ldc + c]) =
                    make_float2(v0, v1);
            }
        }
    }
}

// ---------------- host launcher ----------------
extern "C" void kernel_launch(void* const* d_in, const int* in_sizes, int n_in,
                              void* d_out, int out_size) {
    const float* inputs = (const float*)d_in[0];
    const float* ln1_g  = (const float*)d_in[1];
    const float* ln1_b  = (const float*)d_in[2];
    const float* w_qkv  = (const float*)d_in[3];
    const float* w_proj = (const float*)d_in[4];
    const float* b_proj = (const float*)d_in[5];
    const float* ln2_g  = (const float*)d_in[6];
    const float* ln2_b  = (const float*)d_in[7];
    const float* w1     = (const float*)d_in[8];
    const float* b1     = (const float*)d_in[9];
    const float* w2     = (const float*)d_in[10];
    const float* b2     = (const float*)d_in[11];
    float* x = (float*)d_out;

    float *ph, *pqkv, *pscores, *pattn, *pmlp;
    cudaGetSymbolAddress((void**)&ph,      g_h);
    cudaGetSymbolAddress((void**)&pqkv,    g_qkv);
    cudaGetSymbolAddress((void**)&pscores, g_scores);
    cudaGetSymbolAddress((void**)&pattn,   g_attn);
    cudaGetSymbolAddress((void**)&pmlp,    g_mlp);

    cudaMemcpyAsync(x, inputs, (size_t)ROWS*DD*sizeof(float),
                    cudaMemcpyDeviceToDevice);

    const dim3 blk(256);

    for (int l = 0; l < LNUM; l++) {
        ln_kernel<<<ROWS, blk>>>(x, ln1_g + l*DD, ln1_b + l*DD, ph);

        // qkv = h @ w_qkv[l]   [8192,256]x[256,6144]
        gemm_tf32<0,false><<<dim3(QKV_N/128, ROWS/128, 1), blk>>>(
            ph, w_qkv + (size_t)l*DD*QKV_N, nullptr, nullptr, pqkv,
            ROWS, QKV_N, DD, DD, QKV_N, QKV_N,
            0,0,0,0,0,0, 1.0f);

        // scores = SCALE * Q @ K^T   per (b,h): [1024,256] x [1024,256]^T
        gemm_tf32<0,true><<<dim3(1024/128, 1024/128, 64), blk>>>(
            pqkv, pqkv + INNER, nullptr, nullptr, pscores,
            1024, 1024, DD, QKV_N, QKV_N, 1024,
            (long long)NN_*QKV_N, DD,
            (long long)NN_*QKV_N, DD,
            8LL*1024*1024,        1024LL*1024,
            SCALE_);

        softmax_kernel<<<64*1024, blk>>>(pscores);

        // attn_out = P @ V   per (b,h): [1024,1024]x[1024,256]
        gemm_tf32<0,false><<<dim3(DD/128, 1024/128, 64), blk>>>(
            pscores, pqkv + 2*INNER, nullptr, nullptr, pattn,
            1024, DD, 1024, 1024, QKV_N, INNER,
            8LL*1024*1024,        1024LL*1024,
            (long long)NN_*QKV_N, DD,
            (long long)NN_*INNER, DD,
            1.0f);

        // x = x + attn_out @ w_proj[l] + b_proj[l]
        gemm_tf32<3,false><<<dim3(DD/128, ROWS/128, 1), blk>>>(
            pattn, w_proj + (size_t)l*INNER*DD, b_proj + l*DD, x, x,
            ROWS, DD, INNER, INNER, DD, DD,
            0,0,0,0,0,0, 1.0f);

        ln_kernel<<<ROWS, blk>>>(x, ln2_g + l*DD, ln2_b + l*DD, ph);

        // hidden = gelu(h @ w1[l] + b1[l])
        gemm_tf32<2,false><<<dim3(MM/128, ROWS/128, 1), blk>>>(
            ph, w1 + (size_t)l*DD*MM, b1 + l*MM, nullptr, pmlp,
            ROWS, MM, DD, DD, MM, MM,
            0,0,0,0,0,0, 1.0f);

        // x = x + hidden @ w2[l] + b2[l]
        gemm_tf32<3,false><<<dim3(DD/128, ROWS/128, 1), blk>>>(
            pmlp, w2 + (size_t)l*MM*DD, b2 + l*DD, x, x,
            ROWS, DD, MM, MM, DD, DD,
            0,0,0,0,0,0, 1.0f);
    }
}

// round 5
// speedup vs baseline: 1.6214x; 1.6214x over previous
#include <cuda_runtime.h>
#include <cuda_bf16.h>
#include <math.h>

// Problem constants
#define LNUM 4
#define DD   256
#define HH   8
#define INNER 2048
#define MM   1024
#define BB   8
#define NN_  1024
#define ROWS (BB*NN_)       // 8192
#define QKV_N (3*INNER)     // 6144
#define SCALE_ 0.0625f

// ---------------- device scratch ----------------
__device__ float g_h[(size_t)ROWS*DD];
__device__ float g_qkv[(size_t)ROWS*QKV_N];
__device__ float g_scores[(size_t)64*1024*1024];
__device__ float g_attn[(size_t)ROWS*INNER];
__device__ float g_mlp[(size_t)ROWS*MM];

__device__ __forceinline__ unsigned f2tf32(float x) {
    unsigned r;
    asm("cvt.rna.tf32.f32 %0, %1;" : "=r"(r) : "f"(x));
    return r;
}

// ---------------- LayerNorm ----------------
__global__ void ln_kernel(const float* __restrict__ x,
                          const float* __restrict__ g,
                          const float* __restrict__ b,
                          float* __restrict__ out) {
    const int row = blockIdx.x;
    const int t   = threadIdx.x;
    float v = x[(size_t)row*DD + t];
    float s1 = v, s2 = v*v;
    #pragma unroll
    for (int o = 16; o > 0; o >>= 1) {
        s1 += __shfl_down_sync(0xffffffffu, s1, o);
        s2 += __shfl_down_sync(0xffffffffu, s2, o);
    }
    __shared__ float w1[8], w2[8];
    const int lane = t & 31, wid = t >> 5;
    if (lane == 0) { w1[wid] = s1; w2[wid] = s2; }
    __syncthreads();
    __shared__ float smu, srs;
    if (t == 0) {
        float a = 0.f, c = 0.f;
        #pragma unroll
        for (int i = 0; i < 8; i++) { a += w1[i]; c += w2[i]; }
        float mu  = a / DD;
        float var = c / DD - mu*mu;
        smu = mu;
        srs = rsqrtf(var + 1e-5f);
    }
    __syncthreads();
    out[(size_t)row*DD + t] = (v - smu) * srs * g[t] + b[t];
}

// ---------------- softmax over 1024 cols ----------------
__global__ void softmax_kernel(float* __restrict__ s) {
    float* p = s + (size_t)blockIdx.x * 1024;
    const int t = threadIdx.x;
    float v0 = p[t], v1 = p[t+256], v2 = p[t+512], v3 = p[t+768];
    float m = fmaxf(fmaxf(v0, v1), fmaxf(v2, v3));
    #pragma unroll
    for (int o = 16; o > 0; o >>= 1) m = fmaxf(m, __shfl_down_sync(0xffffffffu, m, o));
    __shared__ float wm[8];
    const int lane = t & 31, wid = t >> 5;
    if (lane == 0) wm[wid] = m;
    __syncthreads();
    __shared__ float bm;
    if (t == 0) {
        float a = wm[0];
        #pragma unroll
        for (int i = 1; i < 8; i++) a = fmaxf(a, wm[i]);
        bm = a;
    }
    __syncthreads();
    m = bm;
    v0 = expf(v0 - m); v1 = expf(v1 - m); v2 = expf(v2 - m); v3 = expf(v3 - m);
    float s1 = v0 + v1 + v2 + v3;
    #pragma unroll
    for (int o = 16; o > 0; o >>= 1) s1 += __shfl_down_sync(0xffffffffu, s1, o);
    __shared__ float ws[8];
    if (lane == 0) ws[wid] = s1;
    __syncthreads();
    __shared__ float bs_;
    if (t == 0) {
        float a = 0.f;
        #pragma unroll
        for (int i = 0; i < 8; i++) a += ws[i];
        bs_ = a;
    }
    __syncthreads();
    const float inv = 1.f / bs_;
    p[t] = v0*inv; p[t+256] = v1*inv; p[t+512] = v2*inv; p[t+768] = v3*inv;
}

// ---------------- tf32 GEMM: ldmatrix + swizzled smem ----------------------
// C = alpha * A[M,K] @ op(B) (+bias)(+gelu|+residual); row-major.
// TB=false: B is [K,N]. TB=true: B is [N,K] (A @ B^T).
// Block 128x64, 8 warps (4 row x 2 col), warp 32x32, K-chunk 32, dbl-buffered.
// Smem: As[m][32w], Bs (stores B^T) [n][32w]; 16B chunk swizzle c ^= (row&7).
// EPI: 0 none, 1 +bias, 2 +bias+gelu, 3 +bias+residual
template<int EPI, bool TB>
__global__ void __launch_bounds__(256)
gemm_tf32(const float* __restrict__ A, const float* __restrict__ B,
          const float* __restrict__ bias, const float* __restrict__ res,
          float* __restrict__ C,
          int M, int N, int K, int lda, int ldb, int ldc,
          long long sAb, long long sAh, long long sBb, long long sBh,
          long long sCb, long long sCh, float alpha)
{
    const int bb = blockIdx.z >> 3;
    const int hh = blockIdx.z & 7;
    A += (size_t)bb*sAb + (size_t)hh*sAh;
    B += (size_t)bb*sBb + (size_t)hh*sBh;
    C += (size_t)bb*sCb + (size_t)hh*sCh;

    const int row0 = blockIdx.y * 128;
    const int col0 = blockIdx.x * 64;
    const int tid  = threadIdx.x;
    const int lane = tid & 31, wid = tid >> 5;
    const int wr = wid & 3, wc = wid >> 2;   // warp tile: rows wr*32, cols wc*32
    const int g  = lane >> 2, t4 = lane & 3;

    __shared__ unsigned As[2][128][32];   // 32 KB
    __shared__ unsigned Bs[2][64][32];    // 16 KB

    const unsigned asBase = (unsigned)__cvta_generic_to_shared(&As[0][0][0]);
    const unsigned bsBase = (unsigned)__cvta_generic_to_shared(&Bs[0][0][0]);

    // ---- loader geometry
    const int rA  = tid >> 3;          // 0..31 (row step 32)
    const int cAc = tid & 7;           // chunk 0..7
    const int nB  = tid & 63;          // NN: n index
    const int kbB = (tid >> 6) * 8;    // NN: k base (0,8,16,24)

    float4 va[4];
    float  vbS[8];     // NN path
    float4 vbT[2];     // TB path

    auto ldg = [&](int kk) {
        #pragma unroll
        for (int i = 0; i < 4; i++)
            va[i] = *reinterpret_cast<const float4*>(
                &A[(size_t)(row0 + rA + 32*i)*lda + kk + cAc*4]);
        if (TB) {
            #pragma unroll
            for (int i = 0; i < 2; i++)
                vbT[i] = *reinterpret_cast<const float4*>(
                    &B[(size_t)(col0 + rA + 32*i)*ldb + kk + cAc*4]);
        } else {
            #pragma unroll
            for (int w = 0; w < 8; w++)
                vbS[w] = B[(size_t)(kk + kbB + w)*ldb + col0 + nB];
        }
    };

    auto sts = [&](int buf) {
        #pragma unroll
        for (int i = 0; i < 4; i++) {
            const int m = rA + 32*i;
            uint4 u = make_uint4(f2tf32(va[i].x), f2tf32(va[i].y),
                                 f2tf32(va[i].z), f2tf32(va[i].w));
            *reinterpret_cast<uint4*>(&As[buf][m][(cAc ^ (m&7))*4]) = u;
        }
        if (TB) {
            #pragma unroll
            for (int i = 0; i < 2; i++) {
                const int n = rA + 32*i;
                uint4 u = make_uint4(f2tf32(vbT[i].x), f2tf32(vbT[i].y),
                                     f2tf32(vbT[i].z), f2tf32(vbT[i].w));
                *reinterpret_cast<uint4*>(&Bs[buf][n][(cAc ^ (n&7))*4]) = u;
            }
        } else {
            const int c0 = kbB >> 2;
            uint4 u0 = make_uint4(f2tf32(vbS[0]), f2tf32(vbS[1]),
                                  f2tf32(vbS[2]), f2tf32(vbS[3]));
            uint4 u1 = make_uint4(f2tf32(vbS[4]), f2tf32(vbS[5]),
                                  f2tf32(vbS[6]), f2tf32(vbS[7]));
            *reinterpret_cast<uint4*>(&Bs[buf][nB][((c0  ) ^ (nB&7))*4]) = u0;
            *reinterpret_cast<uint4*>(&Bs[buf][nB][((c0+1) ^ (nB&7))*4]) = u1;
        }
    };

    // ---- per-lane ldmatrix address precompute
    const int ami   = lane >> 3;                 // matrix index 0..3
    const int aHalf = ami >> 1;                  // word-half
    const int aRoff = ((ami & 1) << 3) + (lane & 7);
    int aM[2], aSw[2];
    #pragma unroll
    for (int mf = 0; mf < 2; mf++) {
        aM[mf]  = wr*32 + mf*16 + aRoff;
        aSw[mf] = aM[mf] & 7;
    }
    const int bHalf = (lane >> 3) & 1;
    const int bRoff = ((lane >> 4) << 3) + (lane & 7);
    int bN[2], bSw[2];
    #pragma unroll
    for (int nf = 0; nf < 2; nf++) {
        bN[nf]  = wc*32 + nf*16 + bRoff;
        bSw[nf] = bN[nf] & 7;
    }

    float acc[2][4][4] = {};

    auto compute = [&](int buf) {
        const unsigned aBuf = asBase + buf*16384;
        const unsigned bBuf = bsBase + buf*8192;
        #pragma unroll
        for (int k8 = 0; k8 < 4; k8++) {
            uint4 af[2], bf[2];
            #pragma unroll
            for (int mf = 0; mf < 2; mf++) {
                unsigned addr = aBuf + aM[mf]*128
                              + ((((k8<<1) + aHalf) ^ aSw[mf]) << 4);
                asm volatile(
                    "ldmatrix.sync.aligned.m8n8.x4.shared.b16 {%0,%1,%2,%3}, [%4];"
                    : "=r"(af[mf].x), "=r"(af[mf].y), "=r"(af[mf].z), "=r"(af[mf].w)
                    : "r"(addr));
            }
            #pragma unroll
            for (int nf = 0; nf < 2; nf++) {
                unsigned addr = bBuf + bN[nf]*128
                              + ((((k8<<1) + bHalf) ^ bSw[nf]) << 4);
                asm volatile(
                    "ldmatrix.sync.aligned.m8n8.x4.shared.b16 {%0,%1,%2,%3}, [%4];"
                    : "=r"(bf[nf].x), "=r"(bf[nf].y), "=r"(bf[nf].z), "=r"(bf[nf].w)
                    : "r"(addr));
            }
            unsigned bp[4][2] = {
                {bf[0].x, bf[0].y}, {bf[0].z, bf[0].w},
                {bf[1].x, bf[1].y}, {bf[1].z, bf[1].w}};
            #pragma unroll
            for (int m = 0; m < 2; m++)
                #pragma unroll
                for (int n = 0; n < 4; n++)
                    asm volatile(
                        "mma.sync.aligned.m16n8k8.row.col.f32.tf32.tf32.f32 "
                        "{%0,%1,%2,%3}, {%4,%5,%6,%7}, {%8,%9}, {%0,%1,%2,%3};"
                        : "+f"(acc[m][n][0]), "+f"(acc[m][n][1]),
                          "+f"(acc[m][n][2]), "+f"(acc[m][n][3])
                        : "r"(af[m].x), "r"(af[m].y), "r"(af[m].z), "r"(af[m].w),
                          "r"(bp[n][0]), "r"(bp[n][1]));
        }
    };

    const int nch = K >> 5;
    ldg(0);
    sts(0);
    __syncthreads();
    for (int ch = 0; ch < nch; ch++) {
        const int buf = ch & 1;
        if (ch + 1 < nch) ldg((ch + 1) * 32);
        compute(buf);
        if (ch + 1 < nch) {
            sts(buf ^ 1);
            __syncthreads();
        }
    }

    // epilogue
    #pragma unroll
    for (int m = 0; m < 2; m++) {
        const int rbase = row0 + wr*32 + m*16 + g;
        #pragma unroll
        for (int n = 0; n < 4; n++) {
            const int c = col0 + wc*32 + n*8 + 2*t4;
            #pragma unroll
            for (int h = 0; h < 2; h++) {
                const int r = rbase + h*8;
                float v0 = acc[m][n][2*h+0] * alpha;
                float v1 = acc[m][n][2*h+1] * alpha;
                if (EPI >= 1) { v0 += bias[c]; v1 += bias[c+1]; }
                if (EPI == 2) {
                    v0 = 0.5f * v0 * (1.0f + erff(v0 * 0.70710678118654752f));
                    v1 = 0.5f * v1 * (1.0f + erff(v1 * 0.70710678118654752f));
                }
                if (EPI == 3) {
                    v0 += res[(size_t)r*ldc + c];
                    v1 += res[(size_t)r*ldc + c + 1];
                }
                *reinterpret_cast<float2*>(&C[(size_t)r*ldc + c]) =
                    make_float2(v0, v1);
            }
        }
    }
}

// ---------------- host launcher ----------------
extern "C" void kernel_launch(void* const* d_in, const int* in_sizes, int n_in,
                              void* d_out, int out_size) {
    const float* inputs = (const float*)d_in[0];
    const float* ln1_g  = (const float*)d_in[1];
    const float* ln1_b  = (const float*)d_in[2];
    const float* w_qkv  = (const float*)d_in[3];
    const float* w_proj = (const float*)d_in[4];
    const float* b_proj = (const float*)d_in[5];
    const float* ln2_g  = (const float*)d_in[6];
    const float* ln2_b  = (const float*)d_in[7];
    const float* w1     = (const float*)d_in[8];
    const float* b1     = (const float*)d_in[9];
    const float* w2     = (const float*)d_in[10];
    const float* b2     = (const float*)d_in[11];
    float* x = (float*)d_out;

    float *ph, *pqkv, *pscores, *pattn, *pmlp;
    cudaGetSymbolAddress((void**)&ph,      g_h);
    cudaGetSymbolAddress((void**)&pqkv,    g_qkv);
    cudaGetSymbolAddress((void**)&pscores, g_scores);
    cudaGetSymbolAddress((void**)&pattn,   g_attn);
    cudaGetSymbolAddress((void**)&pmlp,    g_mlp);

    cudaMemcpyAsync(x, inputs, (size_t)ROWS*DD*sizeof(float),
                    cudaMemcpyDeviceToDevice);

    const dim3 blk(256);

    for (int l = 0; l < LNUM; l++) {
        ln_kernel<<<ROWS, blk>>>(x, ln1_g + l*DD, ln1_b + l*DD, ph);

        // qkv = h @ w_qkv[l]   [8192,256]x[256,6144]
        gemm_tf32<0,false><<<dim3(QKV_N/64, ROWS/128, 1), blk>>>(
            ph, w_qkv + (size_t)l*DD*QKV_N, nullptr, nullptr, pqkv,
            ROWS, QKV_N, DD, DD, QKV_N, QKV_N,
            0,0,0,0,0,0, 1.0f);

        // scores = SCALE * Q @ K^T   per (b,h)
        gemm_tf32<0,true><<<dim3(1024/64, 1024/128, 64), blk>>>(
            pqkv, pqkv + INNER, nullptr, nullptr, pscores,
            1024, 1024, DD, QKV_N, QKV_N, 1024,
            (long long)NN_*QKV_N, DD,
            (long long)NN_*QKV_N, DD,
            8LL*1024*1024,        1024LL*1024,
            SCALE_);

        softmax_kernel<<<64*1024, blk>>>(pscores);

        // attn_out = P @ V   per (b,h)
        gemm_tf32<0,false><<<dim3(DD/64, 1024/128, 64), blk>>>(
            pscores, pqkv + 2*INNER, nullptr, nullptr, pattn,
            1024, DD, 1024, 1024, QKV_N, INNER,
            8LL*1024*1024,        1024LL*1024,
            (long long)NN_*QKV_N, DD,
            (long long)NN_*INNER, DD,
            1.0f);

        // x = x + attn_out @ w_proj[l] + b_proj[l]
        gemm_tf32<3,false><<<dim3(DD/64, ROWS/128, 1), blk>>>(
            pattn, w_proj + (size_t)l*INNER*DD, b_proj + l*DD, x, x,
            ROWS, DD, INNER, INNER, DD, DD,
            0,0,0,0,0,0, 1.0f);

        ln_kernel<<<ROWS, blk>>>(x, ln2_g + l*DD, ln2_b + l*DD, ph);

        // hidden = gelu(h @ w1[l] + b1[l])
        gemm_tf32<2,false><<<dim3(MM/64, ROWS/128, 1), blk>>>(
            ph, w1 + (size_t)l*DD*MM, b1 + l*MM, nullptr, pmlp,
            ROWS, MM, DD, DD, MM, MM,
            0,0,0,0,0,0, 1.0f);

        // x = x + hidden @ w2[l] + b2[l]
        gemm_tf32<3,false><<<dim3(DD/64, ROWS/128, 1), blk>>>(
            pmlp, w2 + (size_t)l*MM*DD, b2 + l*DD, x, x,
            ROWS, DD, MM, MM, DD, DD,
            0,0,0,0,0,0, 1.0f);
    }
}

// round 6
// speedup vs baseline: 1.7840x; 1.1003x over previous
#include <cuda_runtime.h>
#include <cuda_bf16.h>
#include <math.h>

// Problem constants
#define LNUM 4
#define DD   256
#define HH   8
#define INNER 2048
#define MM   1024
#define BB   8
#define NN_  1024
#define ROWS (BB*NN_)       // 8192
#define QKV_N (3*INNER)     // 6144
#define SCALE_ 0.0625f

// ---------------- device scratch ----------------
__device__ float g_h[(size_t)ROWS*DD];
__device__ float g_qkv[(size_t)ROWS*QKV_N];
__device__ float g_scores[(size_t)64*1024*1024];
__device__ float g_attn[(size_t)ROWS*INNER];
__device__ float g_mlp[(size_t)ROWS*MM];

__device__ __forceinline__ unsigned f2tf32(float x) {
    unsigned r;
    asm("cvt.rna.tf32.f32 %0, %1;" : "=r"(r) : "f"(x));
    return r;
}

// ---------------- LayerNorm: warp per row, 8 rows/block --------------------
__global__ void ln_kernel(const float* __restrict__ x,
                          const float* __restrict__ g,
                          const float* __restrict__ b,
                          float* __restrict__ out) {
    const int row  = blockIdx.x*8 + (threadIdx.x >> 5);
    const int lane = threadIdx.x & 31;
    const float* px = x + (size_t)row*DD;
    float4 a = *reinterpret_cast<const float4*>(px + lane*4);
    float4 c = *reinterpret_cast<const float4*>(px + 128 + lane*4);
    float s1 = a.x+a.y+a.z+a.w + c.x+c.y+c.z+c.w;
    float s2 = a.x*a.x+a.y*a.y+a.z*a.z+a.w*a.w
             + c.x*c.x+c.y*c.y+c.z*c.z+c.w*c.w;
    #pragma unroll
    for (int o = 16; o > 0; o >>= 1) {
        s1 += __shfl_xor_sync(0xffffffffu, s1, o);
        s2 += __shfl_xor_sync(0xffffffffu, s2, o);
    }
    const float mu = s1 * (1.0f/DD);
    const float rs = rsqrtf(s2 * (1.0f/DD) - mu*mu + 1e-5f);
    float4 g0 = *reinterpret_cast<const float4*>(g + lane*4);
    float4 g1 = *reinterpret_cast<const float4*>(g + 128 + lane*4);
    float4 b0 = *reinterpret_cast<const float4*>(b + lane*4);
    float4 b1 = *reinterpret_cast<const float4*>(b + 128 + lane*4);
    float* po = out + (size_t)row*DD;
    *reinterpret_cast<float4*>(po + lane*4) = make_float4(
        (a.x-mu)*rs*g0.x + b0.x, (a.y-mu)*rs*g0.y + b0.y,
        (a.z-mu)*rs*g0.z + b0.z, (a.w-mu)*rs*g0.w + b0.w);
    *reinterpret_cast<float4*>(po + 128 + lane*4) = make_float4(
        (c.x-mu)*rs*g1.x + b1.x, (c.y-mu)*rs*g1.y + b1.y,
        (c.z-mu)*rs*g1.z + b1.z, (c.w-mu)*rs*g1.w + b1.w);
}

// ---------------- tf32 GEMM: ldmatrix + swizzled smem ----------------------
// C = f(alpha * A[M,K] @ op(B)); row-major.
// TB=false: B is [K,N]. TB=true: B is [N,K] (A @ B^T).
// Block 128x64, 8 warps (4 row x 2 col), warp 32x32, K-chunk 32, dbl-buffered.
// EPI: 0 none, 2 +bias+gelu, 3 +bias+residual,
//      4 rowsum-normalize (PV: out = acc / rowsum(A)), 5 exp(alpha*acc)
template<int EPI, bool TB>
__global__ void __launch_bounds__(256)
gemm_tf32(const float* __restrict__ A, const float* __restrict__ B,
          const float* __restrict__ bias, const float* __restrict__ res,
          float* __restrict__ C,
          int M, int N, int K, int lda, int ldb, int ldc,
          long long sAb, long long sAh, long long sBb, long long sBh,
          long long sCb, long long sCh, float alpha)
{
    const int bb = blockIdx.z >> 3;
    const int hh = blockIdx.z & 7;
    A += (size_t)bb*sAb + (size_t)hh*sAh;
    B += (size_t)bb*sBb + (size_t)hh*sBh;
    C += (size_t)bb*sCb + (size_t)hh*sCh;

    const int row0 = blockIdx.y * 128;
    const int col0 = blockIdx.x * 64;
    const int tid  = threadIdx.x;
    const int lane = tid & 31, wid = tid >> 5;
    const int wr = wid & 3, wc = wid >> 2;
    const int g  = lane >> 2, t4 = lane & 3;

    __shared__ unsigned As[2][128][32];   // 32 KB
    __shared__ unsigned Bs[2][64][32];    // 16 KB
    __shared__ float rowsumS[128];

    const unsigned asBase = (unsigned)__cvta_generic_to_shared(&As[0][0][0]);
    const unsigned bsBase = (unsigned)__cvta_generic_to_shared(&Bs[0][0][0]);

    const int rA  = tid >> 3;          // 0..31
    const int cAc = tid & 7;           // chunk 0..7
    const int nB  = tid & 63;
    const int kbB = (tid >> 6) * 8;

    float4 va[4];
    float  vbS[8];
    float4 vbT[2];
    float  rsum[4] = {0.f, 0.f, 0.f, 0.f};

    auto ldg = [&](int kk) {
        #pragma unroll
        for (int i = 0; i < 4; i++)
            va[i] = *reinterpret_cast<const float4*>(
                &A[(size_t)(row0 + rA + 32*i)*lda + kk + cAc*4]);
        if (TB) {
            #pragma unroll
            for (int i = 0; i < 2; i++)
                vbT[i] = *reinterpret_cast<const float4*>(
                    &B[(size_t)(col0 + rA + 32*i)*ldb + kk + cAc*4]);
        } else {
            #pragma unroll
            for (int w = 0; w < 8; w++)
                vbS[w] = B[(size_t)(kk + kbB + w)*ldb + col0 + nB];
        }
    };

    auto sts = [&](int buf) {
        #pragma unroll
        for (int i = 0; i < 4; i++) {
            const int m = rA + 32*i;
            uint4 u = make_uint4(f2tf32(va[i].x), f2tf32(va[i].y),
                                 f2tf32(va[i].z), f2tf32(va[i].w));
            if (EPI == 4) {
                rsum[i] += __uint_as_float(u.x) + __uint_as_float(u.y)
                         + __uint_as_float(u.z) + __uint_as_float(u.w);
            }
            *reinterpret_cast<uint4*>(&As[buf][m][(cAc ^ (m&7))*4]) = u;
        }
        if (TB) {
            #pragma unroll
            for (int i = 0; i < 2; i++) {
                const int n = rA + 32*i;
                uint4 u = make_uint4(f2tf32(vbT[i].x), f2tf32(vbT[i].y),
                                     f2tf32(vbT[i].z), f2tf32(vbT[i].w));
                *reinterpret_cast<uint4*>(&Bs[buf][n][(cAc ^ (n&7))*4]) = u;
            }
        } else {
            const int c0 = kbB >> 2;
            uint4 u0 = make_uint4(f2tf32(vbS[0]), f2tf32(vbS[1]),
                                  f2tf32(vbS[2]), f2tf32(vbS[3]));
            uint4 u1 = make_uint4(f2tf32(vbS[4]), f2tf32(vbS[5]),
                                  f2tf32(vbS[6]), f2tf32(vbS[7]));
            *reinterpret_cast<uint4*>(&Bs[buf][nB][((c0  ) ^ (nB&7))*4]) = u0;
            *reinterpret_cast<uint4*>(&Bs[buf][nB][((c0+1) ^ (nB&7))*4]) = u1;
        }
    };

    // ldmatrix address precompute
    const int ami   = lane >> 3;
    const int aHalf = ami >> 1;
    const int aRoff = ((ami & 1) << 3) + (lane & 7);
    int aM[2], aSw[2];
    #pragma unroll
    for (int mf = 0; mf < 2; mf++) {
        aM[mf]  = wr*32 + mf*16 + aRoff;
        aSw[mf] = aM[mf] & 7;
    }
    const int bHalf = (lane >> 3) & 1;
    const int bRoff = ((lane >> 4) << 3) + (lane & 7);
    int bN[2], bSw[2];
    #pragma unroll
    for (int nf = 0; nf < 2; nf++) {
        bN[nf]  = wc*32 + nf*16 + bRoff;
        bSw[nf] = bN[nf] & 7;
    }

    float acc[2][4][4] = {};

    auto compute = [&](int buf) {
        const unsigned aBuf = asBase + buf*16384;
        const unsigned bBuf = bsBase + buf*8192;
        #pragma unroll
        for (int k8 = 0; k8 < 4; k8++) {
            uint4 af[2], bf[2];
            #pragma unroll
            for (int mf = 0; mf < 2; mf++) {
                unsigned addr = aBuf + aM[mf]*128
                              + ((((k8<<1) + aHalf) ^ aSw[mf]) << 4);
                asm volatile(
                    "ldmatrix.sync.aligned.m8n8.x4.shared.b16 {%0,%1,%2,%3}, [%4];"
                    : "=r"(af[mf].x), "=r"(af[mf].y), "=r"(af[mf].z), "=r"(af[mf].w)
                    : "r"(addr));
            }
            #pragma unroll
            for (int nf = 0; nf < 2; nf++) {
                unsigned addr = bBuf + bN[nf]*128
                              + ((((k8<<1) + bHalf) ^ bSw[nf]) << 4);
                asm volatile(
                    "ldmatrix.sync.aligned.m8n8.x4.shared.b16 {%0,%1,%2,%3}, [%4];"
                    : "=r"(bf[nf].x), "=r"(bf[nf].y), "=r"(bf[nf].z), "=r"(bf[nf].w)
                    : "r"(addr));
            }
            unsigned bp[4][2] = {
                {bf[0].x, bf[0].y}, {bf[0].z, bf[0].w},
                {bf[1].x, bf[1].y}, {bf[1].z, bf[1].w}};
            #pragma unroll
            for (int m = 0; m < 2; m++)
                #pragma unroll
                for (int n = 0; n < 4; n++)
                    asm volatile(
                        "mma.sync.aligned.m16n8k8.row.col.f32.tf32.tf32.f32 "
                        "{%0,%1,%2,%3}, {%4,%5,%6,%7}, {%8,%9}, {%0,%1,%2,%3};"
                        : "+f"(acc[m][n][0]), "+f"(acc[m][n][1]),
                          "+f"(acc[m][n][2]), "+f"(acc[m][n][3])
                        : "r"(af[m].x), "r"(af[m].y), "r"(af[m].z), "r"(af[m].w),
                          "r"(bp[n][0]), "r"(bp[n][1]));
        }
    };

    const int nch = K >> 5;
    ldg(0);
    sts(0);
    __syncthreads();
    for (int ch = 0; ch < nch; ch++) {
        const int buf = ch & 1;
        if (ch + 1 < nch) ldg((ch + 1) * 32);
        compute(buf);
        if (ch + 1 < nch) {
            sts(buf ^ 1);
            __syncthreads();
        }
    }

    // rowsum reduce (PV normalize path)
    if (EPI == 4) {
        #pragma unroll
        for (int i = 0; i < 4; i++) {
            float s = rsum[i];
            s += __shfl_xor_sync(0xffffffffu, s, 1);
            s += __shfl_xor_sync(0xffffffffu, s, 2);
            s += __shfl_xor_sync(0xffffffffu, s, 4);
            if ((tid & 7) == 0) rowsumS[rA + 32*i] = s;
        }
        __syncthreads();
    }

    // epilogue
    #pragma unroll
    for (int m = 0; m < 2; m++) {
        const int rb = wr*32 + m*16 + g;
        #pragma unroll
        for (int n = 0; n < 4; n++) {
            const int c = col0 + wc*32 + n*8 + 2*t4;
            #pragma unroll
            for (int h = 0; h < 2; h++) {
                const int rl = rb + h*8;
                const int r  = row0 + rl;
                float v0 = acc[m][n][2*h+0] * alpha;
                float v1 = acc[m][n][2*h+1] * alpha;
                if (EPI == 2 || EPI == 3) { v0 += bias[c]; v1 += bias[c+1]; }
                if (EPI == 2) {
                    v0 = 0.5f * v0 * (1.0f + erff(v0 * 0.70710678118654752f));
                    v1 = 0.5f * v1 * (1.0f + erff(v1 * 0.70710678118654752f));
                }
                if (EPI == 3) {
                    v0 += res[(size_t)r*ldc + c];
                    v1 += res[(size_t)r*ldc + c + 1];
                }
                if (EPI == 4) {
                    const float inv = 1.0f / rowsumS[rl];
                    v0 *= inv; v1 *= inv;
                }
                if (EPI == 5) {
                    v0 = __expf(v0); v1 = __expf(v1);
                }
                *reinterpret_cast<float2*>(&C[(size_t)r*ldc + c]) =
                    make_float2(v0, v1);
            }
        }
    }
}

// ---------------- host launcher ----------------
extern "C" void kernel_launch(void* const* d_in, const int* in_sizes, int n_in,
                              void* d_out, int out_size) {
    const float* inputs = (const float*)d_in[0];
    const float* ln1_g  = (const float*)d_in[1];
    const float* ln1_b  = (const float*)d_in[2];
    const float* w_qkv  = (const float*)d_in[3];
    const float* w_proj = (const float*)d_in[4];
    const float* b_proj = (const float*)d_in[5];
    const float* ln2_g  = (const float*)d_in[6];
    const float* ln2_b  = (const float*)d_in[7];
    const float* w1     = (const float*)d_in[8];
    const float* b1     = (const float*)d_in[9];
    const float* w2     = (const float*)d_in[10];
    const float* b2     = (const float*)d_in[11];
    float* x = (float*)d_out;

    float *ph, *pqkv, *pscores, *pattn, *pmlp;
    cudaGetSymbolAddress((void**)&ph,      g_h);
    cudaGetSymbolAddress((void**)&pqkv,    g_qkv);
    cudaGetSymbolAddress((void**)&pscores, g_scores);
    cudaGetSymbolAddress((void**)&pattn,   g_attn);
    cudaGetSymbolAddress((void**)&pmlp,    g_mlp);

    cudaMemcpyAsync(x, inputs, (size_t)ROWS*DD*sizeof(float),
                    cudaMemcpyDeviceToDevice);

    const dim3 blk(256);

    for (int l = 0; l < LNUM; l++) {
        ln_kernel<<<ROWS/8, blk>>>(x, ln1_g + l*DD, ln1_b + l*DD, ph);

        // qkv = h @ w_qkv[l]
        gemm_tf32<0,false><<<dim3(QKV_N/64, ROWS/128, 1), blk>>>(
            ph, w_qkv + (size_t)l*DD*QKV_N, nullptr, nullptr, pqkv,
            ROWS, QKV_N, DD, DD, QKV_N, QKV_N,
            0,0,0,0,0,0, 1.0f);

        // scoresExp = exp(SCALE * Q @ K^T)   per (b,h)
        gemm_tf32<5,true><<<dim3(1024/64, 1024/128, 64), blk>>>(
            pqkv, pqkv + INNER, nullptr, nullptr, pscores,
            1024, 1024, DD, QKV_N, QKV_N, 1024,
            (long long)NN_*QKV_N, DD,
            (long long)NN_*QKV_N, DD,
            8LL*1024*1024,        1024LL*1024,
            SCALE_);

        // attn_out = (scoresExp @ V) / rowsum   per (b,h)
        gemm_tf32<4,false><<<dim3(DD/64, 1024/128, 64), blk>>>(
            pscores, pqkv + 2*INNER, nullptr, nullptr, pattn,
            1024, DD, 1024, 1024, QKV_N, INNER,
            8LL*1024*1024,        1024LL*1024,
            (long long)NN_*QKV_N, DD,
            (long long)NN_*INNER, DD,
            1.0f);

        // x = x + attn_out @ w_proj[l] + b_proj[l]
        gemm_tf32<3,false><<<dim3(DD/64, ROWS/128, 1), blk>>>(
            pattn, w_proj + (size_t)l*INNER*DD, b_proj + l*DD, x, x,
            ROWS, DD, INNER, INNER, DD, DD,
            0,0,0,0,0,0, 1.0f);

        ln_kernel<<<ROWS/8, blk>>>(x, ln2_g + l*DD, ln2_b + l*DD, ph);

        // hidden = gelu(h @ w1[l] + b1[l])
        gemm_tf32<2,false><<<dim3(MM/64, ROWS/128, 1), blk>>>(
            ph, w1 + (size_t)l*DD*MM, b1 + l*MM, nullptr, pmlp,
            ROWS, MM, DD, DD, MM, MM,
            0,0,0,0,0,0, 1.0f);

        // x = x + hidden @ w2[l] + b2[l]
        gemm_tf32<3,false><<<dim3(DD/64, ROWS/128, 1), blk>>>(
            pmlp, w2 + (size_t)l*MM*DD, b2 + l*DD, x, x,
            ROWS, DD, MM, MM, DD, DD,
            0,0,0,0,0,0, 1.0f);
    }
}